// round 16
// baseline (speedup 1.0000x reference)
#include <cuda_runtime.h>
#include <cuda_fp16.h>
#include <math.h>
#include <cstdint>

#define KTOT 2048
#define NJ   40
#define NT   5
#define NKC  128            // 2048/16 k-steps total
#define NBIAS 16
#define NSPL 8              // prep K-splits
#define SMARGIN 0.31f
#define RSCALE 2048.0f
#define RINV   (1.0f / 2048.0f)
#define PXB    17408u       // prep: 64 rows * 272 B
#define MXB    34816u       // main: 128 rows * 272 B
#define BBYTES 10240u       // 640 uint4 interleaved hi/lo fragments
#define PBUF   (PXB + BBYTES)
#define MBUF   (MXB + BBYTES)

// ---- device scratch -------------------------------------------------------
__device__ float g_c[NJ];
__device__ float g_cpart[NBIAS * NJ];
__device__ float g_part[NSPL * KTOT * NJ];
__device__ uint4 g_Wf[NKC * NT * 32];   // Wp frags  {hi.x,hi.y,lo.x,lo.y}
__device__ uint4 g_Bf[NKC * NT * 32];   // W12 frags {hi.x,hi.y,lo.x,lo.y}

// ---- helpers --------------------------------------------------------------
__device__ __forceinline__ uint32_t smem_u32(const void* p) {
    uint32_t a;
    asm("{ .reg .u64 t; cvta.to.shared.u64 t, %1; cvt.u32.u64 %0, t; }" : "=r"(a) : "l"(p));
    return a;
}
__device__ __forceinline__ void cp_async16(uint32_t d, const void* s) {
    asm volatile("cp.async.cg.shared.global [%0], [%1], 16;" :: "r"(d), "l"(s));
}
__device__ __forceinline__ void cp_commit() { asm volatile("cp.async.commit_group;" ::: "memory"); }
__device__ __forceinline__ void cp_wait0()  { asm volatile("cp.async.wait_group 0;" ::: "memory"); }
__device__ __forceinline__ void cp_wait1()  { asm volatile("cp.async.wait_group 1;" ::: "memory"); }

#define MMA_F16(d, a0, a1, a2, a3, b0, b1)                                    \
    asm volatile("mma.sync.aligned.m16n8k16.row.col.f32.f16.f16.f32 "         \
                 "{%0,%1,%2,%3}, {%4,%5,%6,%7}, {%8,%9}, {%0,%1,%2,%3};\n"    \
                 : "+f"(d[0]), "+f"(d[1]), "+f"(d[2]), "+f"(d[3])             \
                 : "r"(a0), "r"(a1), "r"(a2), "r"(a3), "r"(b0), "r"(b1))

__device__ __forceinline__ void cvt_split_h(float2 v, unsigned& h, unsigned& l) {
    __half2 hh = __floats2half2_rn(v.x, v.y);
    float2 hf = __half22float2(hh);
    __half2 ll = __floats2half2_rn((v.x - hf.x) * RSCALE, (v.y - hf.y) * RSCALE);
    h = *reinterpret_cast<unsigned*>(&hh);
    l = *reinterpret_cast<unsigned*>(&ll);
}
__device__ __forceinline__ unsigned pack_h2(float a, float b) {
    __half2 h = __floats2half2_rn(a, b);
    return *reinterpret_cast<unsigned*>(&h);
}
__device__ __forceinline__ uint4 make_frag(const float v[4]) {
    float rr[4];
#pragma unroll
    for (int e = 0; e < 4; e++) {
        __half h = __float2half_rn(v[e]);
        rr[e] = (v[e] - __half2float(h)) * RSCALE;
    }
    return make_uint4(pack_h2(v[0], v[1]), pack_h2(v[2], v[3]),
                      pack_h2(rr[0], rr[1]), pack_h2(rr[2], rr[3]));
}

// ---------------------------------------------------------------------------
// Kernel A: blocks 0..127 pack Wp=[Wcls|Wfl] into interleaved fragments;
//           blocks 128..143 bias partials; block 128 inits g_c raw biases.
// ---------------------------------------------------------------------------
__global__ __launch_bounds__(256)
void wfrag_bias_kernel(const float* __restrict__ Wcls, const float* __restrict__ Wfl,
                       const float* __restrict__ benc,
                       const float* __restrict__ bcls, const float* __restrict__ bfl) {
    int b = blockIdx.x;
    int tid = threadIdx.x;
    if (b < 128) {
        __shared__ float wp[16 * NJ];
        for (int i = tid; i < 16 * NJ; i += 256) {
            int m = i / NJ, n = i - (i / NJ) * NJ;
            int gm = b * 16 + m;
            wp[i] = (n < 20) ? Wcls[(size_t)gm * 20 + n] : Wfl[(size_t)gm * 20 + (n - 20)];
        }
        __syncthreads();
        if (tid < 160) {
            int lane = tid & 31, nt = tid >> 5;
            int m0 = (lane & 3) * 2, n = nt * 8 + (lane >> 2);
            float v[4];
#pragma unroll
            for (int e = 0; e < 4; e++)
                v[e] = wp[(m0 + (e >> 1) * 8 + (e & 1)) * NJ + n];
            g_Wf[b * 160 + tid] = make_frag(v);
        }
        return;
    }
    __shared__ float sw[4][NJ];
    int bb = b - 128;
    if (tid >= 128) return;
    int k = bb * 128 + tid;
    int warp = tid >> 5, lane = tid & 31;
    float bv = benc[k];
    float w[NJ];
#pragma unroll
    for (int j4 = 0; j4 < 5; j4++) {
        float4 v = *(const float4*)(Wcls + (size_t)k * 20 + j4 * 4);
        w[j4*4+0] = v.x; w[j4*4+1] = v.y; w[j4*4+2] = v.z; w[j4*4+3] = v.w;
    }
#pragma unroll
    for (int j4 = 0; j4 < 5; j4++) {
        float4 v = *(const float4*)(Wfl + (size_t)k * 20 + j4 * 4);
        w[20+j4*4+0] = v.x; w[20+j4*4+1] = v.y; w[20+j4*4+2] = v.z; w[20+j4*4+3] = v.w;
    }
#pragma unroll
    for (int j = 0; j < NJ; j++) {
        float s = bv * w[j];
#pragma unroll
        for (int o = 16; o > 0; o >>= 1) s += __shfl_xor_sync(0xffffffffu, s, o);
        if (lane == 0) sw[warp][j] = s;
    }
    __syncthreads();
    if (tid < NJ) {
        g_cpart[bb * NJ + tid] = (sw[0][tid] + sw[1][tid]) + (sw[2][tid] + sw[3][tid]);
        if (bb == 0) g_c[tid] = (tid < 20) ? bcls[tid] : bfl[tid - 20];
    }
}

// ---------------------------------------------------------------------------
// staging helpers
// ---------------------------------------------------------------------------
__device__ __forceinline__ void stage64(uint32_t smb, int buf, int gchunk,
                                        const float* __restrict__ src, size_t rowbase,
                                        const uint4* __restrict__ frag, int tid) {
    uint32_t xd = smb + (uint32_t)buf * PBUF;
#pragma unroll
    for (int it = 0; it < 8; it++) {
        int q = it * 128 + tid;
        int rw = q >> 4, c4 = q & 15;
        cp_async16(xd + (uint32_t)(rw * 272 + c4 * 16),
                   src + (rowbase + rw) * KTOT + gchunk * 64 + c4 * 4);
    }
    uint32_t bd = xd + PXB;
    const uint4* fsrc = frag + (size_t)gchunk * 640;
#pragma unroll
    for (int it = 0; it < 5; it++) {
        int q = it * 128 + tid;
        cp_async16(bd + (uint32_t)q * 16, fsrc + q);
    }
}

// 128 rows, 256 threads
__device__ __forceinline__ void stage128_256(uint32_t smb, int buf, int gchunk,
                                             const float* __restrict__ src, size_t rowbase,
                                             const uint4* __restrict__ frag, int tid) {
    uint32_t xd = smb + (uint32_t)buf * MBUF;
#pragma unroll
    for (int it = 0; it < 8; it++) {
        int q = it * 256 + tid;
        int rw = q >> 4, c4 = q & 15;
        cp_async16(xd + (uint32_t)(rw * 272 + c4 * 16),
                   src + (rowbase + rw) * KTOT + gchunk * 64 + c4 * 4);
    }
    uint32_t bd = xd + MXB;
    const uint4* fsrc = frag + (size_t)gchunk * 640;
#pragma unroll
    for (int it = 0; it < 3; it++) {
        int q = it * 256 + tid;
        if (q < 640) cp_async16(bd + (uint32_t)q * 16, fsrc + q);
    }
}

// ---------------------------------------------------------------------------
// Kernel B: prep GEMM (unchanged, validated)
// ---------------------------------------------------------------------------
__global__ __launch_bounds__(128)
void prep_mma_kernel(const float* __restrict__ Wenc) {
    extern __shared__ char sm[];
    const int tid = threadIdx.x;
    const int warp = tid >> 5, lane = tid & 31;
    const int c2 = (lane & 3) * 2;
    const int tile = blockIdx.x & 31, split = blockIdx.x >> 5;
    const size_t tilebase = (size_t)tile * 64;
    const int chunk0 = split * 4;

    const uint32_t smb = smem_u32(sm);
    stage64(smb, 0, chunk0, Wenc, tilebase, g_Wf, tid);
    cp_commit(); cp_wait0();
    __syncthreads();

    float acc1[NT][4], acc2[NT][4];
#pragma unroll
    for (int nt = 0; nt < NT; nt++)
#pragma unroll
        for (int e = 0; e < 4; e++) { acc1[nt][e] = 0.f; acc2[nt][e] = 0.f; }

    const uint32_t xoff = (uint32_t)((warp * 16 + (lane >> 2)) * 272 + c2 * 4);

    for (int c = 0; c < 4; c++) {
        int buf = c & 1;
        if (c + 1 < 4) { stage64(smb, buf ^ 1, chunk0 + c + 1, Wenc, tilebase, g_Wf, tid); cp_commit(); }
        uint32_t base = smb + (uint32_t)buf * PBUF;
        uint32_t xa = base + xoff;
        uint32_t ba = base + PXB + (uint32_t)lane * 16;
#pragma unroll
        for (int s = 0; s < 4; s++) {
            float2 v00, v10, v01, v11;
            asm("ld.shared.v2.f32 {%0, %1}, [%2];" : "=f"(v00.x), "=f"(v00.y) : "r"(xa + s * 64));
            asm("ld.shared.v2.f32 {%0, %1}, [%2];" : "=f"(v10.x), "=f"(v10.y) : "r"(xa + s * 64 + 8 * 272));
            asm("ld.shared.v2.f32 {%0, %1}, [%2];" : "=f"(v01.x), "=f"(v01.y) : "r"(xa + s * 64 + 32));
            asm("ld.shared.v2.f32 {%0, %1}, [%2];" : "=f"(v11.x), "=f"(v11.y) : "r"(xa + s * 64 + 32 + 8 * 272));
            unsigned ah0, ah1, ah2, ah3, al0, al1, al2, al3;
            cvt_split_h(v00, ah0, al0);
            cvt_split_h(v10, ah1, al1);
            cvt_split_h(v01, ah2, al2);
            cvt_split_h(v11, ah3, al3);
#pragma unroll
            for (int nt = 0; nt < NT; nt++) {
                uint4 w;
                uint32_t fo = (uint32_t)((s * NT + nt) * 512);
                asm("ld.shared.v4.u32 {%0, %1, %2, %3}, [%4];"
                    : "=r"(w.x), "=r"(w.y), "=r"(w.z), "=r"(w.w) : "r"(ba + fo));
                MMA_F16(acc1[nt], ah0, ah1, ah2, ah3, w.x, w.y);
                MMA_F16(acc2[nt], al0, al1, al2, al3, w.x, w.y);
                MMA_F16(acc2[nt], ah0, ah1, ah2, ah3, w.z, w.w);
            }
        }
        if (c + 1 < 4) cp_wait0();
        __syncthreads();
    }

    int krow = (int)tilebase + warp * 16 + (lane >> 2);
#pragma unroll
    for (int nt = 0; nt < NT; nt++) {
        float* p0 = g_part + ((size_t)split * KTOT + krow) * NJ + nt * 8 + c2;
        float* p1 = p0 + 8 * NJ;
        *(float2*)p0 = make_float2(acc1[nt][0] + acc2[nt][0] * RINV,
                                   acc1[nt][1] + acc2[nt][1] * RINV);
        *(float2*)p1 = make_float2(acc1[nt][2] + acc2[nt][2] * RINV,
                                   acc1[nt][3] + acc2[nt][3] * RINV);
    }
}

// ---------------------------------------------------------------------------
// Kernel C: coalesced reduce of 8 partial slabs -> interleaved W12 fragments.
// ---------------------------------------------------------------------------
__global__ __launch_bounds__(256)
void bsplit_kernel() {
    int b = blockIdx.x;
    int tid = threadIdx.x;
    __shared__ float w12[64 * NJ];
    float r[10];
#pragma unroll
    for (int i = 0; i < 10; i++) r[i] = 0.f;
    size_t cellbase = (size_t)b * 2560;
#pragma unroll
    for (int s = 0; s < NSPL; s++) {
        const float* src = g_part + (size_t)s * (KTOT * NJ) + cellbase;
#pragma unroll
        for (int i = 0; i < 10; i++) r[i] += src[tid + i * 256];
    }
#pragma unroll
    for (int i = 0; i < 10; i++) w12[tid + i * 256] = r[i];
    __syncthreads();
#pragma unroll
    for (int i = 0; i < 3; i++) {
        int f = tid + i * 256;
        if (f < 640) {
            int kc16l = f / 160;
            int rem = f - kc16l * 160;
            int nt = rem >> 5, lane = rem & 31;
            int k0l = kc16l * 16 + (lane & 3) * 2;
            int n = nt * 8 + (lane >> 2);
            float v[4];
#pragma unroll
            for (int e = 0; e < 4; e++)
                v[e] = w12[(k0l + (e >> 1) * 8 + (e & 1)) * NJ + n];
            g_Bf[b * 640 + f] = make_frag(v);
        }
    }
}

// ---------------------------------------------------------------------------
// Main kernel: CTA = 128 rows / 256 threads / grid 128 (1 CTA per SM, balanced).
// Warp tile = 32 rows (2 row-tiles) x 40 cols -> each B-fragment LDS.128 feeds
// 6 MMAs.  Warps 0-3: row-groups, k-steps 0-1; warps 4-7: same rows, k 2-3.
// 3-stage cp.async pipeline.  Validated fused epilogue per row-tile.
// ---------------------------------------------------------------------------
__global__ __launch_bounds__(256)
void mma_main_kernel(const float* __restrict__ x, float* __restrict__ out) {
    extern __shared__ char sm[];
    __shared__ float cb[NJ];
    const int tid = threadIdx.x;
    const int warp = tid >> 5, lane = tid & 31;
    const int rw = warp & 3, kh = warp >> 2;
    const int c2 = (lane & 3) * 2;
    const size_t growbase = (size_t)blockIdx.x * 128;

    if (tid < NJ) {
        float s = g_c[tid];
#pragma unroll
        for (int p = 0; p < NBIAS; p++) s += g_cpart[p * NJ + tid];
        cb[tid] = s;
    }

    const uint32_t smb = smem_u32(sm);
    stage128_256(smb, 0, 0, x, growbase, g_Bf, tid); cp_commit();
    stage128_256(smb, 1, 1, x, growbase, g_Bf, tid); cp_commit();
    cp_wait1();
    __syncthreads();

    float acc1[2][NT][4], acc2[2][NT][4];
#pragma unroll
    for (int rt = 0; rt < 2; rt++)
#pragma unroll
        for (int nt = 0; nt < NT; nt++)
#pragma unroll
            for (int e = 0; e < 4; e++) { acc1[rt][nt][e] = 0.f; acc2[rt][nt][e] = 0.f; }

    // rows: rw*32 + rt*16 + (lane>>2) / +8
    const uint32_t xoff = (uint32_t)((rw * 32 + (lane >> 2)) * 272 + c2 * 4);

    int buf = 0;
    for (int c = 0; c < 32; c++) {
        if (c + 2 < 32) {
            int nb = buf + 2; if (nb >= 3) nb -= 3;
            stage128_256(smb, nb, c + 2, x, growbase, g_Bf, tid);
            cp_commit();
        }
        uint32_t base = smb + (uint32_t)buf * MBUF;
        uint32_t xa = base + xoff;
        uint32_t ba = base + MXB + (uint32_t)lane * 16;
#pragma unroll
        for (int ss = 0; ss < 2; ss++) {
            int s = kh * 2 + ss;
            unsigned ah[2][4], al[2][4];
#pragma unroll
            for (int rt = 0; rt < 2; rt++) {
                uint32_t xr = xa + (uint32_t)(rt * 16 * 272) + s * 64;
                float2 v00, v10, v01, v11;
                asm("ld.shared.v2.f32 {%0, %1}, [%2];" : "=f"(v00.x), "=f"(v00.y) : "r"(xr));
                asm("ld.shared.v2.f32 {%0, %1}, [%2];" : "=f"(v10.x), "=f"(v10.y) : "r"(xr + 8 * 272));
                asm("ld.shared.v2.f32 {%0, %1}, [%2];" : "=f"(v01.x), "=f"(v01.y) : "r"(xr + 32));
                asm("ld.shared.v2.f32 {%0, %1}, [%2];" : "=f"(v11.x), "=f"(v11.y) : "r"(xr + 32 + 8 * 272));
                cvt_split_h(v00, ah[rt][0], al[rt][0]);
                cvt_split_h(v10, ah[rt][1], al[rt][1]);
                cvt_split_h(v01, ah[rt][2], al[rt][2]);
                cvt_split_h(v11, ah[rt][3], al[rt][3]);
            }
#pragma unroll
            for (int nt = 0; nt < NT; nt++) {
                uint4 w;
                uint32_t fo = (uint32_t)((s * NT + nt) * 512);
                asm("ld.shared.v4.u32 {%0, %1, %2, %3}, [%4];"
                    : "=r"(w.x), "=r"(w.y), "=r"(w.z), "=r"(w.w) : "r"(ba + fo));
#pragma unroll
                for (int rt = 0; rt < 2; rt++) {
                    MMA_F16(acc1[rt][nt], ah[rt][0], ah[rt][1], ah[rt][2], ah[rt][3], w.x, w.y);
                    MMA_F16(acc2[rt][nt], al[rt][0], al[rt][1], al[rt][2], al[rt][3], w.x, w.y);
                    MMA_F16(acc2[rt][nt], ah[rt][0], ah[rt][1], ah[rt][2], ah[rt][3], w.z, w.w);
                }
            }
        }
        if (c + 1 < 32) {
            if (c + 2 < 32) cp_wait1(); else cp_wait0();
            __syncthreads();
        }
        if (++buf == 3) buf = 0;
    }

    // ---- combine k-halves via smem (stride 21 floats: conflict-free) ------
    float* ex = (float*)sm;                 // buf0 region; chunk 31 read buf1
    if (kh == 1) {
#pragma unroll
        for (int rt = 0; rt < 2; rt++) {
            float* dst = ex + (size_t)((rw * 2 + rt) * 32 + lane) * 21;
#pragma unroll
            for (int nt = 0; nt < NT; nt++)
#pragma unroll
                for (int e = 0; e < 4; e++)
                    dst[nt * 4 + e] = acc1[rt][nt][e] + acc2[rt][nt][e] * RINV;
        }
    }
    __syncthreads();
    if (kh == 1) return;

#pragma unroll
    for (int rt = 0; rt < 2; rt++) {
        float fin[NT][4];
        {
            const float* src = ex + (size_t)((rw * 2 + rt) * 32 + lane) * 21;
#pragma unroll
            for (int nt = 0; nt < NT; nt++)
#pragma unroll
                for (int e = 0; e < 4; e++)
                    fin[nt][e] = acc1[rt][nt][e] + acc2[rt][nt][e] * RINV + src[nt * 4 + e];
        }

        int row0 = (int)growbase + rw * 32 + rt * 16 + (lane >> 2);
        float scl[2];
        float ecls[2][6];
#pragma unroll
        for (int half = 0; half < 2; half++) {
            float m1 = -1e30f, m2 = -1e30f, mn2 = 1e30f;
#pragma unroll
            for (int nt = 0; nt < NT; nt++)
#pragma unroll
                for (int e = 0; e < 2; e++) {
                    int j = nt * 8 + c2 + e;
                    float v = fin[nt][half * 2 + e] + cb[j];
                    if (j < 20) m1 = fmaxf(m1, v);
                    else { m2 = fmaxf(m2, v); mn2 = fminf(mn2, v); }
                }
            m1 = fmaxf(m1, __shfl_xor_sync(0xffffffffu, m1, 1));
            m1 = fmaxf(m1, __shfl_xor_sync(0xffffffffu, m1, 2));
            m2 = fmaxf(m2, __shfl_xor_sync(0xffffffffu, m2, 1));
            m2 = fmaxf(m2, __shfl_xor_sync(0xffffffffu, m2, 2));
            mn2 = fminf(mn2, __shfl_xor_sync(0xffffffffu, mn2, 1));
            mn2 = fminf(mn2, __shfl_xor_sync(0xffffffffu, mn2, 2));
            float s1 = 0.f, s2 = 0.f;
#pragma unroll
            for (int nt = 0; nt < NT; nt++)
#pragma unroll
                for (int e = 0; e < 2; e++) {
                    int j = nt * 8 + c2 + e;
                    float v = fin[nt][half * 2 + e] + cb[j];
                    if (j < 20) {
                        float ex2 = __expf(v - m1);
                        if (nt < 3) ecls[half][nt * 2 + e] = ex2;
                        s1 += ex2;
                    } else {
                        s2 += __expf(v - m2);
                    }
                }
            s1 += __shfl_xor_sync(0xffffffffu, s1, 1);
            s1 += __shfl_xor_sync(0xffffffffu, s1, 2);
            s2 += __shfl_xor_sync(0xffffffffu, s2, 1);
            s2 += __shfl_xor_sync(0xffffffffu, s2, 2);
            float pred = 1.0f / s1;
            float tau  = __expf(mn2 - m2) / s2;
            scl[half] = (pred >= tau + SMARGIN) ? pred : 0.0f;
        }
#pragma unroll
        for (int half = 0; half < 2; half++) {
            float* orow = out + (size_t)(row0 + half * 8) * 20;
#pragma unroll
            for (int nt = 0; nt < 3; nt++) {
                int j0 = nt * 8 + c2;
                if (j0 < 20)
                    *(float2*)(orow + j0) = make_float2(ecls[half][nt * 2 + 0] * scl[half],
                                                        ecls[half][nt * 2 + 1] * scl[half]);
            }
        }
    }
}

// ---------------------------------------------------------------------------
extern "C" void kernel_launch(void* const* d_in, const int* in_sizes, int n_in,
                              void* d_out, int out_size) {
    const float* x    = (const float*)d_in[0];
    const float* Wenc = (const float*)d_in[1];
    const float* benc = (const float*)d_in[2];
    const float* Wcls = (const float*)d_in[3];
    const float* bcls = (const float*)d_in[4];
    const float* Wfl  = (const float*)d_in[5];
    const float* bfl  = (const float*)d_in[6];
    float* out = (float*)d_out;
    int M = in_sizes[0] / KTOT;   // 16384

    static int smset = 0;
    if (!smset) {
        cudaFuncSetAttribute(mma_main_kernel,
                             cudaFuncAttributeMaxDynamicSharedMemorySize, 3 * MBUF);
        cudaFuncSetAttribute(prep_mma_kernel,
                             cudaFuncAttributeMaxDynamicSharedMemorySize, 2 * PBUF);
        smset = 1;
    }

    wfrag_bias_kernel<<<144, 256>>>(Wcls, Wfl, benc, bcls, bfl);
    prep_mma_kernel<<<32 * NSPL, 128, 2 * PBUF>>>(Wenc);
    bsplit_kernel<<<32, 256>>>();
    mma_main_kernel<<<M / 128, 256, 3 * MBUF>>>(x, out);
}